// round 11
// baseline (speedup 1.0000x reference)
#include <cuda_runtime.h>
#include <cuda_fp16.h>
#include <stdint.h>

// ---------------- problem constants ----------------
#define BB 4
#define LL 10000
#define KK 16
#define II 256
#define OO 256
#define MTOT (BB * LL)          // 40000
#define MTILES 313              // ceil(40000 / 128)

// ---------------- device scratch ----------------
__device__ __align__(16) __half g_xh[(size_t)BB * LL * II];     // x in fp16
__device__ __align__(16) __half g_maskT[(size_t)KK * OO * II];  // mask transposed: [k][o][i]

// ---------------- helpers ----------------
__device__ __forceinline__ uint32_t smem_to_u32(const void* p) {
    uint32_t a;
    asm("{ .reg .u64 t; cvta.to.shared.u64 t, %1; cvt.u32.u64 %0, t; }"
        : "=r"(a) : "l"(p));
    return a;
}
__device__ __forceinline__ void cp_async16(uint32_t dst, const void* src) {
    asm volatile("cp.async.cg.shared.global [%0], [%1], 16;" :: "r"(dst), "l"(src));
}
#define CP_COMMIT() asm volatile("cp.async.commit_group;" ::: "memory")
#define CP_WAIT2()  asm volatile("cp.async.wait_group 2;" ::: "memory")
#define CP_WAIT1()  asm volatile("cp.async.wait_group 1;" ::: "memory")
#define CP_WAIT0()  asm volatile("cp.async.wait_group 0;" ::: "memory")

#define BAR_SYNC(id)   asm volatile("bar.sync %0, 160;"   :: "r"(id) : "memory")
#define BAR_ARRIVE(id) asm volatile("bar.arrive %0, 160;" :: "r"(id) : "memory")

__device__ __forceinline__ void ldmx4(uint32_t& r0, uint32_t& r1, uint32_t& r2, uint32_t& r3,
                                      uint32_t addr) {
    asm volatile("ldmatrix.sync.aligned.m8n8.x4.shared.b16 {%0,%1,%2,%3}, [%4];"
                 : "=r"(r0), "=r"(r1), "=r"(r2), "=r"(r3) : "r"(addr));
}
__device__ __forceinline__ void mma16816(float* c, const uint32_t* a, uint32_t b0, uint32_t b1) {
    asm volatile(
        "mma.sync.aligned.m16n8k16.row.col.f32.f16.f16.f32 "
        "{%0,%1,%2,%3}, {%4,%5,%6,%7}, {%8,%9}, {%0,%1,%2,%3};"
        : "+f"(c[0]), "+f"(c[1]), "+f"(c[2]), "+f"(c[3])
        : "r"(a[0]), "r"(a[1]), "r"(a[2]), "r"(a[3]), "r"(b0), "r"(b1));
}

// ---------------- merged prologue ----------------
__global__ void __launch_bounds__(1024)
prologue_kernel(const float* __restrict__ x, const float* __restrict__ mask) {
    if (blockIdx.x < 2500) {
        int t = blockIdx.x * 1024 + threadIdx.x;
        float4 v = ((const float4*)x)[t];
        __half2* dst = ((__half2*)g_xh) + 2 * t;
        dst[0] = __floats2half2_rn(v.x, v.y);
        dst[1] = __floats2half2_rn(v.z, v.w);
    } else {
        __shared__ float ts[32][33];
        int bb  = blockIdx.x - 2500;         // 0..1023
        int k   = bb >> 6;                   // 16 experts
        int rem = bb & 63;
        int i0  = (rem >> 3) * 32;
        int o0  = (rem & 7) * 32;
        int tx  = threadIdx.x & 31;
        int ty  = threadIdx.x >> 5;
        ts[ty][tx] = mask[((size_t)k * II + (i0 + ty)) * OO + o0 + tx];
        __syncthreads();
        g_maskT[((size_t)k * OO + (o0 + ty)) * II + i0 + tx] = __float2half(ts[tx][ty]);
    }
}

// ---------------- main kernel ----------------
// CTA tile: 128 (M) x 64 (N). 4 compute warps (64x32 each) + 1 producer warp.
// 3-stage cp.async pipeline driven solely by the producer warp; handoff via
// named barriers: full[s] = id s (0..2), free[s] = id 3+s (3..5), count 160.
// 74KB smem/CTA -> 3 CTAs/SM; grid (313,4) = 1252 CTAs / 444 slots = 2.82 waves.
#define SM_IDX   0
#define SM_STAGE 2048
#define STAGE_BYTES 24576
#define A_BYTES  16384
#define DYN_SMEM (SM_STAGE + 3 * STAGE_BYTES)   // 75776
#define NTHREADS 160

// Producer-warp chunk issue: 32 threads cover A (1024 x 16B) + B (512 x 16B).
__device__ __forceinline__ void issue_chunk_p(int c, uint32_t stage, const int* sIdx,
                                              int n0, int tp) {
    const int kexp  = c >> 2;
    const int ibase = (c & 3) * 64;
    const uint32_t Ab = stage;
    const uint32_t Bb = stage + A_BYTES;

    // A: thread tp owns rows 4*tp .. 4*tp+3 (each row: 8 x 16B)
    const int r0 = tp * 4;
#pragma unroll
    for (int rr = 0; rr < 4; rr++) {
        const int row = r0 + rr;
        const int li  = row >> 2, b = row & 3;
        const int jr  = sIdx[li * 16 + kexp];
        const __half* src = g_xh + ((size_t)(b * LL + jr)) * II + ibase;
        const uint32_t base = (uint32_t)(row * 128);
        const uint32_t ph   = (uint32_t)((row & 7) << 4);
#pragma unroll
        for (int seg = 0; seg < 8; seg++) {
            cp_async16(Ab + ((base + seg * 16u) ^ ph), src + seg * 8);
        }
    }
    // B: thread tp owns rows 2*tp, 2*tp+1
    const int rb0 = tp * 2;
#pragma unroll
    for (int rr = 0; rr < 2; rr++) {
        const int row = rb0 + rr;
        const __half* src = g_maskT + ((size_t)(kexp * OO + n0 + row)) * II + ibase;
        const uint32_t base = (uint32_t)(row * 128);
        const uint32_t ph   = (uint32_t)((row & 7) << 4);
#pragma unroll
        for (int seg = 0; seg < 8; seg++) {
            cp_async16(Bb + ((base + seg * 16u) ^ ph), src + seg * 8);
        }
    }
}

__global__ void __launch_bounds__(NTHREADS, 3)
piconv_mma_kernel(const int* __restrict__ idx,
                  const float* __restrict__ bias,
                  float* __restrict__ out) {
    extern __shared__ char sm[];
    const uint32_t sb = smem_to_u32(sm);
    const int tid    = threadIdx.x;
    const int lane   = tid & 31;
    const int wid    = tid >> 5;            // 0..3 compute, 4 producer
    const int tile   = blockIdx.x;          // M tile (128 rows)
    const int n0     = blockIdx.y * 64;     // N tile
    const int l0     = tile * 32;

    // Stage gather indices (32 l-values x 16 k), clamped for the tail tile
    int* sIdx = (int*)(sm + SM_IDX);
#pragma unroll
    for (int e = tid; e < 512; e += NTHREADS) {
        int li = e >> 4, kk = e & 15;
        int l = l0 + li;
        if (l > LL - 1) l = LL - 1;
        sIdx[e] = idx[l * KK + kk];
    }
    __syncthreads();

    if (wid == 4) {
        // ---------------- producer warp ----------------
        const int tp = lane;
        for (int c = 0; c < 64; c++) {
            const int s = c % 3;
            if (c >= 3) BAR_SYNC(3 + s);                 // wait consumers done with stage s
            issue_chunk_p(c, sb + SM_STAGE + s * STAGE_BYTES, sIdx, n0, tp);
            CP_COMMIT();
            if (c >= 2) {
                CP_WAIT2();                              // chunk c-2 landed
                BAR_ARRIVE((c - 2) % 3);                 // full[(c-2)%3]
            }
        }
        CP_WAIT1();
        BAR_ARRIVE(62 % 3);                              // full[2]
        CP_WAIT0();
        BAR_ARRIVE(63 % 3);                              // full[0]
        return;                                          // no epilogue work
    }

    // ---------------- compute warps (0..3): 64x32 each ----------------
    const int warp_m = wid >> 1;            // 0..1  (64 rows each)
    const int warp_n = wid & 1;             // 0..1  (32 cols each)

    float acc[4][4][4];
#pragma unroll
    for (int a = 0; a < 4; a++)
#pragma unroll
        for (int n = 0; n < 4; n++)
#pragma unroll
            for (int q = 0; q < 4; q++) acc[a][n][q] = 0.f;

    // Per-lane ldmatrix address invariants
    const int rA        = warp_m * 64 + (lane & 15);      // am adds +16 rows (row&7 invariant)
    const uint32_t aRow = (uint32_t)rA * 128u;
    const uint32_t aPh  = (uint32_t)((rA & 7) << 4);
    const int colAh     = (lane >> 4) * 16;
    const int rBb       = warp_n * 32 + (lane & 7) + ((lane >> 4) << 3);  // nb adds +16 rows
    const uint32_t bPh  = (uint32_t)((lane & 7) << 4);
    const int colBh     = ((lane >> 3) & 1) * 16;

    for (int c = 0; c < 64; c++) {
        const int s = c % 3;
        BAR_SYNC(s);                                      // wait stage full

        const uint32_t Ab = sb + SM_STAGE + s * STAGE_BYTES;
        const uint32_t Bb = Ab + A_BYTES;

#pragma unroll
        for (int ks = 0; ks < 4; ks++) {
            uint32_t a[4][4];
            const uint32_t offA = (uint32_t)(ks * 32 + colAh) ^ aPh;
#pragma unroll
            for (int am = 0; am < 4; am++)
                ldmx4(a[am][0], a[am][1], a[am][2], a[am][3],
                      Ab + aRow + (uint32_t)am * 2048u + offA);

            const uint32_t offB = (uint32_t)(ks * 32 + colBh) ^ bPh;
            uint32_t b[2][4];
#pragma unroll
            for (int nb = 0; nb < 2; nb++) {
                const int rB = rBb + nb * 16;
                ldmx4(b[nb][0], b[nb][1], b[nb][2], b[nb][3],
                      Bb + (uint32_t)rB * 128u + offB);
            }
#pragma unroll
            for (int am = 0; am < 4; am++) {
#pragma unroll
                for (int nb = 0; nb < 2; nb++) {
                    mma16816(acc[am][nb * 2 + 0], a[am], b[nb][0], b[nb][1]);
                    mma16816(acc[am][nb * 2 + 1], a[am], b[nb][2], b[nb][3]);
                }
            }
        }
        BAR_ARRIVE(3 + s);                                // stage free
    }

    // ---- Epilogue: bias add + store (row m -> b = m&3, l = m>>2) ----
    const bool tail = (tile == MTILES - 1);
#pragma unroll
    for (int am = 0; am < 4; am++) {
#pragma unroll
        for (int nn = 0; nn < 4; nn++) {
            const int o = n0 + warp_n * 32 + nn * 8 + (lane & 3) * 2;
            const float2 bz = *(const float2*)&bias[o];
            const int m = tile * 128 + warp_m * 64 + am * 16 + (lane >> 2);
            if (!tail || m < MTOT) {
                float2 v;
                v.x = acc[am][nn][0] + bz.x;
                v.y = acc[am][nn][1] + bz.y;
                *(float2*)&out[((size_t)(m & 3) * LL + (m >> 2)) * OO + o] = v;
            }
            const int m2 = m + 8;
            if (!tail || m2 < MTOT) {
                float2 v;
                v.x = acc[am][nn][2] + bz.x;
                v.y = acc[am][nn][3] + bz.y;
                *(float2*)&out[((size_t)(m2 & 3) * LL + (m2 >> 2)) * OO + o] = v;
            }
        }
    }
}

// ---------------- launch ----------------
extern "C" void kernel_launch(void* const* d_in, const int* in_sizes, int n_in,
                              void* d_out, int out_size) {
    const float* x    = (const float*)d_in[0];   // (4, 10000, 256) fp32
    const int*   idx  = (const int*)d_in[1];     // (10000, 16) int32
    const float* mask = (const float*)d_in[2];   // (16, 256, 256) fp32
    const float* bias = (const float*)d_in[3];   // (256,) fp32
    float*       out  = (float*)d_out;           // (4, 10000, 256) fp32

    (void)in_sizes; (void)n_in; (void)out_size;

    static bool attr_set = false;
    if (!attr_set) {
        cudaFuncSetAttribute(piconv_mma_kernel,
                             cudaFuncAttributeMaxDynamicSharedMemorySize, DYN_SMEM);
        attr_set = true;
    }

    prologue_kernel<<<3524, 1024>>>(x, mask);
    piconv_mma_kernel<<<dim3(MTILES, 4), NTHREADS, DYN_SMEM>>>(idx, bias, out);
}

// round 12
// speedup vs baseline: 1.6663x; 1.6663x over previous
#include <cuda_runtime.h>
#include <cuda_fp16.h>
#include <stdint.h>

// ---------------- problem constants ----------------
#define BB 4
#define LL 10000
#define KK 16
#define II 256
#define OO 256
#define MTOT (BB * LL)          // 40000
#define MTILES 313              // ceil(40000 / 128)

// ---------------- device scratch ----------------
__device__ __align__(16) __half g_xh[(size_t)BB * LL * II];     // x in fp16
__device__ __align__(16) __half g_maskT[(size_t)KK * OO * II];  // mask transposed: [k][o][i]

// ---------------- helpers ----------------
__device__ __forceinline__ uint32_t smem_to_u32(const void* p) {
    uint32_t a;
    asm("{ .reg .u64 t; cvta.to.shared.u64 t, %1; cvt.u32.u64 %0, t; }"
        : "=r"(a) : "l"(p));
    return a;
}
__device__ __forceinline__ void cp_async16(uint32_t dst, const void* src) {
    asm volatile("cp.async.cg.shared.global [%0], [%1], 16;" :: "r"(dst), "l"(src));
}
#define CP_COMMIT() asm volatile("cp.async.commit_group;" ::: "memory")
#define CP_WAIT2()  asm volatile("cp.async.wait_group 2;" ::: "memory")
#define CP_WAIT1()  asm volatile("cp.async.wait_group 1;" ::: "memory")
#define CP_WAIT0()  asm volatile("cp.async.wait_group 0;" ::: "memory")

#define BAR_SYNC(id)   asm volatile("bar.sync %0, 160;"   :: "r"(id) : "memory")
#define BAR_ARRIVE(id) asm volatile("bar.arrive %0, 160;" :: "r"(id) : "memory")

__device__ __forceinline__ void ldmx4(uint32_t& r0, uint32_t& r1, uint32_t& r2, uint32_t& r3,
                                      uint32_t addr) {
    asm volatile("ldmatrix.sync.aligned.m8n8.x4.shared.b16 {%0,%1,%2,%3}, [%4];"
                 : "=r"(r0), "=r"(r1), "=r"(r2), "=r"(r3) : "r"(addr));
}
__device__ __forceinline__ void mma16816(float* c, const uint32_t* a, uint32_t b0, uint32_t b1) {
    asm volatile(
        "mma.sync.aligned.m16n8k16.row.col.f32.f16.f16.f32 "
        "{%0,%1,%2,%3}, {%4,%5,%6,%7}, {%8,%9}, {%0,%1,%2,%3};"
        : "+f"(c[0]), "+f"(c[1]), "+f"(c[2]), "+f"(c[3])
        : "r"(a[0]), "r"(a[1]), "r"(a[2]), "r"(a[3]), "r"(b0), "r"(b1));
}

// ---------------- merged prologue ----------------
__global__ void __launch_bounds__(1024)
prologue_kernel(const float* __restrict__ x, const float* __restrict__ mask) {
    if (blockIdx.x < 2500) {
        int t = blockIdx.x * 1024 + threadIdx.x;
        float4 v = ((const float4*)x)[t];
        __half2* dst = ((__half2*)g_xh) + 2 * t;
        dst[0] = __floats2half2_rn(v.x, v.y);
        dst[1] = __floats2half2_rn(v.z, v.w);
    } else {
        __shared__ float ts[32][33];
        int bb  = blockIdx.x - 2500;         // 0..1023
        int k   = bb >> 6;                   // 16 experts
        int rem = bb & 63;
        int i0  = (rem >> 3) * 32;
        int o0  = (rem & 7) * 32;
        int tx  = threadIdx.x & 31;
        int ty  = threadIdx.x >> 5;
        ts[ty][tx] = mask[((size_t)k * II + (i0 + ty)) * OO + o0 + tx];
        __syncthreads();
        g_maskT[((size_t)k * OO + (o0 + ty)) * II + i0 + tx] = __float2half(ts[tx][ty]);
    }
}

// ---------------- main kernel ----------------
// CTA tile: 128 (M) x 64 (N). 4 compute warps (64x32 each) + 1 producer warp.
// 3-stage cp.async pipeline driven by the producer warp with the CONFLICT-FREE
// mapping (consecutive lanes -> consecutive 16B segments of the same row).
// Handoff via named barriers: full[s] = id s (0..2), free[s] = id 3+s, count 160.
// 74KB smem/CTA -> 3 CTAs/SM; grid (313,4) = 1252 CTAs / 444 slots = 2.82 waves.
#define SM_IDX   0
#define SM_STAGE 2048
#define STAGE_BYTES 24576
#define A_BYTES  16384
#define DYN_SMEM (SM_STAGE + 3 * STAGE_BYTES)   // 75776
#define NTHREADS 160

// Producer-warp chunk issue (lane-major, conflict-free):
// A: 1024 x 16B ops (j = 0..31), B: 512 x 16B ops (j = 0..15).
__device__ __forceinline__ void issue_chunk_p(int c, uint32_t stage, const int* sIdx,
                                              int n0, int lane) {
    const int kexp  = c >> 2;
    const int ibase = (c & 3) * 64;
    const uint32_t Ab = stage;
    const uint32_t Bb = stage + A_BYTES;

#pragma unroll
    for (int j = 0; j < 32; j++) {
        const int s   = lane + 32 * j;
        const int row = s >> 3, seg = s & 7;
        const int li  = row >> 2, b = row & 3;
        const int jr  = sIdx[li * 16 + kexp];
        const __half* src = g_xh + ((size_t)(b * LL + jr)) * II + ibase + seg * 8;
        const uint32_t off = (uint32_t)(row * 128 + seg * 16);
        cp_async16(Ab + (off ^ ((row & 7) << 4)), src);
    }
#pragma unroll
    for (int j = 0; j < 16; j++) {
        const int s   = lane + 32 * j;
        const int row = s >> 3, seg = s & 7;
        const __half* src = g_maskT + ((size_t)(kexp * OO + n0 + row)) * II + ibase + seg * 8;
        const uint32_t off = (uint32_t)(row * 128 + seg * 16);
        cp_async16(Bb + (off ^ ((row & 7) << 4)), src);
    }
}

__global__ void __launch_bounds__(NTHREADS, 3)
piconv_mma_kernel(const int* __restrict__ idx,
                  const float* __restrict__ bias,
                  float* __restrict__ out) {
    extern __shared__ char sm[];
    const uint32_t sb = smem_to_u32(sm);
    const int tid    = threadIdx.x;
    const int lane   = tid & 31;
    const int wid    = tid >> 5;            // 0..3 compute, 4 producer
    const int tile   = blockIdx.x;          // M tile (128 rows)
    const int n0     = blockIdx.y * 64;     // N tile
    const int l0     = tile * 32;

    // Stage gather indices (32 l-values x 16 k), clamped for the tail tile
    int* sIdx = (int*)(sm + SM_IDX);
#pragma unroll
    for (int e = tid; e < 512; e += NTHREADS) {
        int li = e >> 4, kk = e & 15;
        int l = l0 + li;
        if (l > LL - 1) l = LL - 1;
        sIdx[e] = idx[l * KK + kk];
    }
    __syncthreads();

    if (wid == 4) {
        // ---------------- producer warp ----------------
        for (int c = 0; c < 64; c++) {
            const int s = c % 3;
            if (c >= 3) BAR_SYNC(3 + s);                 // wait consumers done with stage s
            issue_chunk_p(c, sb + SM_STAGE + s * STAGE_BYTES, sIdx, n0, lane);
            CP_COMMIT();
            if (c >= 2) {
                CP_WAIT2();                              // chunk c-2 landed
                BAR_ARRIVE((c - 2) % 3);                 // full[(c-2)%3]
            }
        }
        CP_WAIT1();
        BAR_ARRIVE(62 % 3);                              // full[2]
        CP_WAIT0();
        BAR_ARRIVE(63 % 3);                              // full[0]
        return;                                          // no epilogue work
    }

    // ---------------- compute warps (0..3): 64x32 each ----------------
    const int warp_m = wid >> 1;            // 0..1  (64 rows each)
    const int warp_n = wid & 1;             // 0..1  (32 cols each)

    float acc[4][4][4];
#pragma unroll
    for (int a = 0; a < 4; a++)
#pragma unroll
        for (int n = 0; n < 4; n++)
#pragma unroll
            for (int q = 0; q < 4; q++) acc[a][n][q] = 0.f;

    // Per-lane ldmatrix address invariants
    const int rA        = warp_m * 64 + (lane & 15);      // am adds +16 rows (row&7 invariant)
    const uint32_t aRow = (uint32_t)rA * 128u;
    const uint32_t aPh  = (uint32_t)((rA & 7) << 4);
    const int colAh     = (lane >> 4) * 16;
    const int rBb       = warp_n * 32 + (lane & 7) + ((lane >> 4) << 3);  // nb adds +16 rows
    const uint32_t bPh  = (uint32_t)((lane & 7) << 4);
    const int colBh     = ((lane >> 3) & 1) * 16;

    for (int c = 0; c < 64; c++) {
        const int s = c % 3;
        BAR_SYNC(s);                                      // wait stage full

        const uint32_t Ab = sb + SM_STAGE + s * STAGE_BYTES;
        const uint32_t Bb = Ab + A_BYTES;

#pragma unroll
        for (int ks = 0; ks < 4; ks++) {
            uint32_t a[4][4];
            const uint32_t offA = (uint32_t)(ks * 32 + colAh) ^ aPh;
#pragma unroll
            for (int am = 0; am < 4; am++)
                ldmx4(a[am][0], a[am][1], a[am][2], a[am][3],
                      Ab + aRow + (uint32_t)am * 2048u + offA);

            const uint32_t offB = (uint32_t)(ks * 32 + colBh) ^ bPh;
            uint32_t b[2][4];
#pragma unroll
            for (int nb = 0; nb < 2; nb++) {
                const int rB = rBb + nb * 16;
                ldmx4(b[nb][0], b[nb][1], b[nb][2], b[nb][3],
                      Bb + (uint32_t)rB * 128u + offB);
            }
#pragma unroll
            for (int am = 0; am < 4; am++) {
#pragma unroll
                for (int nb = 0; nb < 2; nb++) {
                    mma16816(acc[am][nb * 2 + 0], a[am], b[nb][0], b[nb][1]);
                    mma16816(acc[am][nb * 2 + 1], a[am], b[nb][2], b[nb][3]);
                }
            }
        }
        BAR_ARRIVE(3 + s);                                // stage free
    }

    // ---- Epilogue: bias add + store (row m -> b = m&3, l = m>>2) ----
    const bool tail = (tile == MTILES - 1);
#pragma unroll
    for (int am = 0; am < 4; am++) {
#pragma unroll
        for (int nn = 0; nn < 4; nn++) {
            const int o = n0 + warp_n * 32 + nn * 8 + (lane & 3) * 2;
            const float2 bz = *(const float2*)&bias[o];
            const int m = tile * 128 + warp_m * 64 + am * 16 + (lane >> 2);
            if (!tail || m < MTOT) {
                float2 v;
                v.x = acc[am][nn][0] + bz.x;
                v.y = acc[am][nn][1] + bz.y;
                *(float2*)&out[((size_t)(m & 3) * LL + (m >> 2)) * OO + o] = v;
            }
            const int m2 = m + 8;
            if (!tail || m2 < MTOT) {
                float2 v;
                v.x = acc[am][nn][2] + bz.x;
                v.y = acc[am][nn][3] + bz.y;
                *(float2*)&out[((size_t)(m2 & 3) * LL + (m2 >> 2)) * OO + o] = v;
            }
        }
    }
}

// ---------------- launch ----------------
extern "C" void kernel_launch(void* const* d_in, const int* in_sizes, int n_in,
                              void* d_out, int out_size) {
    const float* x    = (const float*)d_in[0];   // (4, 10000, 256) fp32
    const int*   idx  = (const int*)d_in[1];     // (10000, 16) int32
    const float* mask = (const float*)d_in[2];   // (16, 256, 256) fp32
    const float* bias = (const float*)d_in[3];   // (256,) fp32
    float*       out  = (float*)d_out;           // (4, 10000, 256) fp32

    (void)in_sizes; (void)n_in; (void)out_size;

    static bool attr_set = false;
    if (!attr_set) {
        cudaFuncSetAttribute(piconv_mma_kernel,
                             cudaFuncAttributeMaxDynamicSharedMemorySize, DYN_SMEM);
        attr_set = true;
    }

    prologue_kernel<<<3524, 1024>>>(x, mask);
    piconv_mma_kernel<<<dim3(MTILES, 4), NTHREADS, DYN_SMEM>>>(idx, bias, out);
}

// round 13
// speedup vs baseline: 1.9659x; 1.1798x over previous
#include <cuda_runtime.h>
#include <cuda_fp16.h>
#include <stdint.h>

// ---------------- problem constants ----------------
#define BB 4
#define LL 10000
#define KK 16
#define II 256
#define OO 256
#define MTOT (BB * LL)          // 40000
#define MTILES 313              // ceil(40000 / 128)

// ---------------- device scratch ----------------
__device__ __align__(16) __half g_xh[(size_t)BB * LL * II];     // x in fp16
__device__ __align__(16) __half g_maskT[(size_t)KK * OO * II];  // mask transposed: [k][o][i]

// ---------------- helpers ----------------
__device__ __forceinline__ uint32_t smem_to_u32(const void* p) {
    uint32_t a;
    asm("{ .reg .u64 t; cvta.to.shared.u64 t, %1; cvt.u32.u64 %0, t; }"
        : "=r"(a) : "l"(p));
    return a;
}
__device__ __forceinline__ void cp_async16(uint32_t dst, const void* src) {
    asm volatile("cp.async.cg.shared.global [%0], [%1], 16;" :: "r"(dst), "l"(src));
}
#define CP_COMMIT() asm volatile("cp.async.commit_group;" ::: "memory")
#define CP_WAIT1()  asm volatile("cp.async.wait_group 1;" ::: "memory")

__device__ __forceinline__ void ldmx4(uint32_t& r0, uint32_t& r1, uint32_t& r2, uint32_t& r3,
                                      uint32_t addr) {
    asm volatile("ldmatrix.sync.aligned.m8n8.x4.shared.b16 {%0,%1,%2,%3}, [%4];"
                 : "=r"(r0), "=r"(r1), "=r"(r2), "=r"(r3) : "r"(addr));
}
__device__ __forceinline__ void mma16816(float* c, const uint32_t* a, uint32_t b0, uint32_t b1) {
    asm volatile(
        "mma.sync.aligned.m16n8k16.row.col.f32.f16.f16.f32 "
        "{%0,%1,%2,%3}, {%4,%5,%6,%7}, {%8,%9}, {%0,%1,%2,%3};"
        : "+f"(c[0]), "+f"(c[1]), "+f"(c[2]), "+f"(c[3])
        : "r"(a[0]), "r"(a[1]), "r"(a[2]), "r"(a[3]), "r"(b0), "r"(b1));
}

// ---------------- merged prologue ----------------
__global__ void __launch_bounds__(1024)
prologue_kernel(const float* __restrict__ x, const float* __restrict__ mask) {
    if (blockIdx.x < 2500) {
        int t = blockIdx.x * 1024 + threadIdx.x;
        float4 v = ((const float4*)x)[t];
        __half2* dst = ((__half2*)g_xh) + 2 * t;
        dst[0] = __floats2half2_rn(v.x, v.y);
        dst[1] = __floats2half2_rn(v.z, v.w);
    } else {
        __shared__ float ts[32][33];
        int bb  = blockIdx.x - 2500;         // 0..1023
        int k   = bb >> 6;                   // 16 experts
        int rem = bb & 63;
        int i0  = (rem >> 3) * 32;
        int o0  = (rem & 7) * 32;
        int tx  = threadIdx.x & 31;
        int ty  = threadIdx.x >> 5;
        ts[ty][tx] = mask[((size_t)k * II + (i0 + ty)) * OO + o0 + tx];
        __syncthreads();
        g_maskT[((size_t)k * OO + (o0 + ty)) * II + i0 + tx] = __float2half(ts[tx][ty]);
    }
}

// ---------------- main kernel ----------------
// CTA tile: 128 (M) x 64 (N). 4 warps = warp_m(2) x k-group(2): each warp does a
// 64x64 PARTIAL product over 2 of the 4 k16-slices per chunk (A read 1x, B 2x).
// End-of-kernel reduction over k-groups via the (now dead) stage smem.
// 3-stage cp.async lockstep pipeline; 74KB/CTA -> 3 CTAs/SM; grid (313,4) = 2.82 waves.
#define SM_IDX   0
#define SM_STAGE 2048
#define STAGE_BYTES 24576
#define A_BYTES  16384
#define DYN_SMEM (SM_STAGE + 3 * STAGE_BYTES)   // 75776
#define NTHREADS 128

__device__ __forceinline__ void issue_chunk(int c, uint32_t stage, const int* sIdx,
                                            int n0, int tid) {
    const int kexp  = c >> 2;
    const int ibase = (c & 3) * 64;
    const uint32_t Ab = stage;
    const uint32_t Bb = stage + A_BYTES;
    // A: 128 rows x 128B (1024 16B-loads), gathered
#pragma unroll
    for (int j = 0; j < 8; j++) {
        int s   = tid + NTHREADS * j;
        int row = s >> 3, seg = s & 7;
        int li  = row >> 2, b = row & 3;
        int jr  = sIdx[li * 16 + kexp];
        const __half* src = g_xh + ((size_t)(b * LL + jr)) * II + ibase + seg * 8;
        uint32_t off = (uint32_t)(row * 128 + seg * 16);
        cp_async16(Ab + (off ^ ((row & 7) << 4)), src);
    }
    // B: 64 rows (o in [n0, n0+64)) x 128B (512 16B-loads)
#pragma unroll
    for (int j = 0; j < 4; j++) {
        int s   = tid + NTHREADS * j;
        int row = s >> 3, seg = s & 7;
        const __half* src = g_maskT + ((size_t)(kexp * OO + n0 + row)) * II + ibase + seg * 8;
        uint32_t off = (uint32_t)(row * 128 + seg * 16);
        cp_async16(Bb + (off ^ ((row & 7) << 4)), src);
    }
}

__global__ void __launch_bounds__(NTHREADS, 3)
piconv_mma_kernel(const int* __restrict__ idx,
                  const float* __restrict__ bias,
                  float* __restrict__ out) {
    extern __shared__ char sm[];
    const uint32_t sb = smem_to_u32(sm);
    const int tid    = threadIdx.x;
    const int lane   = tid & 31;
    const int wid    = tid >> 5;
    const int warp_m = wid & 1;             // 0..1  (64 rows each)
    const int kg     = wid >> 1;            // 0..1  (k16-slices {0,1} or {2,3})
    const int tile   = blockIdx.x;          // M tile (128 rows)
    const int n0     = blockIdx.y * 64;     // N tile
    const int l0     = tile * 32;

    // Stage gather indices (32 l-values x 16 k), clamped for the tail tile
    int* sIdx = (int*)(sm + SM_IDX);
#pragma unroll
    for (int e = tid; e < 512; e += NTHREADS) {
        int li = e >> 4, kk = e & 15;
        int l = l0 + li;
        if (l > LL - 1) l = LL - 1;
        sIdx[e] = idx[l * KK + kk];
    }
    __syncthreads();

    // 64x64 partial warp tile: acc[am 0..3][nn 0..7][4] = 128 regs
    float acc[4][8][4];
#pragma unroll
    for (int a = 0; a < 4; a++)
#pragma unroll
        for (int n = 0; n < 8; n++)
#pragma unroll
            for (int q = 0; q < 4; q++) acc[a][n][q] = 0.f;

    issue_chunk(0, sb + SM_STAGE + 0 * STAGE_BYTES, sIdx, n0, tid);
    CP_COMMIT();
    issue_chunk(1, sb + SM_STAGE + 1 * STAGE_BYTES, sIdx, n0, tid);
    CP_COMMIT();

    // Per-lane ldmatrix address invariants
    const int rA        = warp_m * 64 + (lane & 15);      // am adds +16 rows (row&7 invariant)
    const uint32_t aRow = (uint32_t)rA * 128u;
    const uint32_t aPh  = (uint32_t)((rA & 7) << 4);
    const int colAh     = (lane >> 4) * 16;
    const int rBb       = (lane & 7) + ((lane >> 4) << 3);  // nb adds +16 rows
    const uint32_t bPh  = (uint32_t)((lane & 7) << 4);
    const int colBh     = ((lane >> 3) & 1) * 16;

    for (int c = 0; c < 64; c++) {
        CP_WAIT1();
        __syncthreads();

        if (c + 2 < 64)
            issue_chunk(c + 2, sb + SM_STAGE + ((c + 2) % 3) * STAGE_BYTES, sIdx, n0, tid);
        CP_COMMIT();

        const uint32_t Ab = sb + SM_STAGE + (c % 3) * STAGE_BYTES;
        const uint32_t Bb = Ab + A_BYTES;

        // This warp handles k16-slices {kg*2, kg*2+1} of the 64-wide chunk
#pragma unroll
        for (int j = 0; j < 2; j++) {
            const int ks = kg * 2 + j;

            // Load full B row-block first (n64 x k16): 4 ldmx4 = 16 regs
            const uint32_t offB = (uint32_t)(ks * 32 + colBh) ^ bPh;
            uint32_t b[4][4];
#pragma unroll
            for (int nb = 0; nb < 4; nb++) {
                const int rB = rBb + nb * 16;
                ldmx4(b[nb][0], b[nb][1], b[nb][2], b[nb][3],
                      Bb + (uint32_t)rB * 128u + offB);
            }

            // Stream A per am (4 regs live), 8 MMAs each
            const uint32_t offA = (uint32_t)(ks * 32 + colAh) ^ aPh;
#pragma unroll
            for (int am = 0; am < 4; am++) {
                uint32_t a[4];
                ldmx4(a[0], a[1], a[2], a[3],
                      Ab + aRow + (uint32_t)am * 2048u + offA);
#pragma unroll
                for (int nb = 0; nb < 4; nb++) {
                    mma16816(acc[am][nb * 2 + 0], a, b[nb][0], b[nb][1]);
                    mma16816(acc[am][nb * 2 + 1], a, b[nb][2], b[nb][3]);
                }
            }
        }
    }

    // ---- k-group reduction via stage smem (dead after last chunk) ----
    __syncthreads();   // all LDSM reads of stage buffers complete
    float* red = (float*)(sm + SM_STAGE);   // 2 x 16KB regions (warp_m 0/1)
    if (kg == 1) {
#pragma unroll
        for (int am = 0; am < 4; am++)
#pragma unroll
            for (int nn = 0; nn < 8; nn++) {
                float4 v;
                v.x = acc[am][nn][0]; v.y = acc[am][nn][1];
                v.z = acc[am][nn][2]; v.w = acc[am][nn][3];
                *(float4*)&red[warp_m * 4096 + ((am * 8 + nn) * 32 + lane) * 4] = v;
            }
    }
    __syncthreads();

    if (kg == 0) {
        const bool tail = (tile == MTILES - 1);
#pragma unroll
        for (int am = 0; am < 4; am++) {
#pragma unroll
            for (int nn = 0; nn < 8; nn++) {
                const float4 p = *(const float4*)
                    &red[warp_m * 4096 + ((am * 8 + nn) * 32 + lane) * 4];
                const int o = n0 + nn * 8 + (lane & 3) * 2;
                const float2 bz = *(const float2*)&bias[o];
                const int m = tile * 128 + warp_m * 64 + am * 16 + (lane >> 2);
                if (!tail || m < MTOT) {
                    float2 v;
                    v.x = acc[am][nn][0] + p.x + bz.x;
                    v.y = acc[am][nn][1] + p.y + bz.y;
                    *(float2*)&out[((size_t)(m & 3) * LL + (m >> 2)) * OO + o] = v;
                }
                const int m2 = m + 8;
                if (!tail || m2 < MTOT) {
                    float2 v;
                    v.x = acc[am][nn][2] + p.z + bz.x;
                    v.y = acc[am][nn][3] + p.w + bz.y;
                    *(float2*)&out[((size_t)(m2 & 3) * LL + (m2 >> 2)) * OO + o] = v;
                }
            }
        }
    }
}

// ---------------- launch ----------------
extern "C" void kernel_launch(void* const* d_in, const int* in_sizes, int n_in,
                              void* d_out, int out_size) {
    const float* x    = (const float*)d_in[0];   // (4, 10000, 256) fp32
    const int*   idx  = (const int*)d_in[1];     // (10000, 16) int32
    const float* mask = (const float*)d_in[2];   // (16, 256, 256) fp32
    const float* bias = (const float*)d_in[3];   // (256,) fp32
    float*       out  = (float*)d_out;           // (4, 10000, 256) fp32

    (void)in_sizes; (void)n_in; (void)out_size;

    static bool attr_set = false;
    if (!attr_set) {
        cudaFuncSetAttribute(piconv_mma_kernel,
                             cudaFuncAttributeMaxDynamicSharedMemorySize, DYN_SMEM);
        attr_set = true;
    }

    prologue_kernel<<<3524, 1024>>>(x, mask);
    piconv_mma_kernel<<<dim3(MTILES, 4), NTHREADS, DYN_SMEM>>>(idx, bias, out);
}

// round 14
// speedup vs baseline: 2.0633x; 1.0495x over previous
#include <cuda_runtime.h>
#include <cuda_fp16.h>
#include <stdint.h>

// ---------------- problem constants ----------------
#define BB 4
#define LL 10000
#define KK 16
#define II 256
#define OO 256
#define MTOT (BB * LL)          // 40000
#define MTILES 313              // ceil(40000 / 128)

// ---------------- device scratch ----------------
__device__ __align__(16) __half g_xh[(size_t)BB * LL * II];     // x in fp16
__device__ __align__(16) __half g_maskT[(size_t)KK * OO * II];  // mask transposed: [k][o][i]

// ---------------- helpers ----------------
__device__ __forceinline__ uint32_t smem_to_u32(const void* p) {
    uint32_t a;
    asm("{ .reg .u64 t; cvta.to.shared.u64 t, %1; cvt.u32.u64 %0, t; }"
        : "=r"(a) : "l"(p));
    return a;
}
__device__ __forceinline__ void cp_async16(uint32_t dst, const void* src) {
    asm volatile("cp.async.cg.shared.global [%0], [%1], 16;" :: "r"(dst), "l"(src));
}
#define CP_COMMIT() asm volatile("cp.async.commit_group;" ::: "memory")
#define CP_WAIT1()  asm volatile("cp.async.wait_group 1;" ::: "memory")

__device__ __forceinline__ void ldmx4(uint32_t& r0, uint32_t& r1, uint32_t& r2, uint32_t& r3,
                                      uint32_t addr) {
    asm volatile("ldmatrix.sync.aligned.m8n8.x4.shared.b16 {%0,%1,%2,%3}, [%4];"
                 : "=r"(r0), "=r"(r1), "=r"(r2), "=r"(r3) : "r"(addr));
}
__device__ __forceinline__ void mma16816(float* c, const uint32_t* a, uint32_t b0, uint32_t b1) {
    asm volatile(
        "mma.sync.aligned.m16n8k16.row.col.f32.f16.f16.f32 "
        "{%0,%1,%2,%3}, {%4,%5,%6,%7}, {%8,%9}, {%0,%1,%2,%3};"
        : "+f"(c[0]), "+f"(c[1]), "+f"(c[2]), "+f"(c[3])
        : "r"(a[0]), "r"(a[1]), "r"(a[2]), "r"(a[3]), "r"(b0), "r"(b1));
}

// ---------------- merged prologue ----------------
__global__ void __launch_bounds__(1024)
prologue_kernel(const float* __restrict__ x, const float* __restrict__ mask) {
    if (blockIdx.x < 2500) {
        int t = blockIdx.x * 1024 + threadIdx.x;
        float4 v = ((const float4*)x)[t];
        __half2* dst = ((__half2*)g_xh) + 2 * t;
        dst[0] = __floats2half2_rn(v.x, v.y);
        dst[1] = __floats2half2_rn(v.z, v.w);
    } else {
        __shared__ float ts[32][33];
        int bb  = blockIdx.x - 2500;         // 0..1023
        int k   = bb >> 6;                   // 16 experts
        int rem = bb & 63;
        int i0  = (rem >> 3) * 32;
        int o0  = (rem & 7) * 32;
        int tx  = threadIdx.x & 31;
        int ty  = threadIdx.x >> 5;
        ts[ty][tx] = mask[((size_t)k * II + (i0 + ty)) * OO + o0 + tx];
        __syncthreads();
        g_maskT[((size_t)k * OO + (o0 + ty)) * II + i0 + tx] = __float2half(ts[tx][ty]);
    }
}

// ---------------- main kernel ----------------
// CTA tile: 128 (M) x 64 (N). 4 warps: 2 (M) x 2 (N), warp tile 64x32.
// 3-stage lockstep cp.async pipeline (R9 sync structure), restructured chunk body:
//   - all B fragments of the chunk loaded upfront (8 LDSM, 32 regs)
//   - A fragments ping-pong double-buffered; LDSM(ks+1) issued before MMA(ks)
//   - cp.async issue placed to cover initial LDSM latency
// 74KB/CTA -> 3 CTAs/SM; grid (313,4) = 1252 CTAs / 444 slots = 2.82 waves.
#define SM_IDX   0
#define SM_STAGE 2048
#define STAGE_BYTES 24576
#define A_BYTES  16384
#define DYN_SMEM (SM_STAGE + 3 * STAGE_BYTES)   // 75776
#define NTHREADS 128

__device__ __forceinline__ void issue_chunk(int c, uint32_t stage, const int* sIdx,
                                            int n0, int tid) {
    const int kexp  = c >> 2;
    const int ibase = (c & 3) * 64;
    const uint32_t Ab = stage;
    const uint32_t Bb = stage + A_BYTES;
    // A: 128 rows x 128B (1024 16B-loads), gathered
#pragma unroll
    for (int j = 0; j < 8; j++) {
        int s   = tid + NTHREADS * j;
        int row = s >> 3, seg = s & 7;
        int li  = row >> 2, b = row & 3;
        int jr  = sIdx[li * 16 + kexp];
        const __half* src = g_xh + ((size_t)(b * LL + jr)) * II + ibase + seg * 8;
        uint32_t off = (uint32_t)(row * 128 + seg * 16);
        cp_async16(Ab + (off ^ ((row & 7) << 4)), src);
    }
    // B: 64 rows (o in [n0, n0+64)) x 128B (512 16B-loads)
#pragma unroll
    for (int j = 0; j < 4; j++) {
        int s   = tid + NTHREADS * j;
        int row = s >> 3, seg = s & 7;
        const __half* src = g_maskT + ((size_t)(kexp * OO + n0 + row)) * II + ibase + seg * 8;
        uint32_t off = (uint32_t)(row * 128 + seg * 16);
        cp_async16(Bb + (off ^ ((row & 7) << 4)), src);
    }
}

__global__ void __launch_bounds__(NTHREADS, 3)
piconv_mma_kernel(const int* __restrict__ idx,
                  const float* __restrict__ bias,
                  float* __restrict__ out) {
    extern __shared__ char sm[];
    const uint32_t sb = smem_to_u32(sm);
    const int tid    = threadIdx.x;
    const int lane   = tid & 31;
    const int wid    = tid >> 5;
    const int warp_m = wid >> 1;            // 0..1  (64 rows each)
    const int warp_n = wid & 1;             // 0..1  (32 cols each)
    const int tile   = blockIdx.x;          // M tile (128 rows)
    const int n0     = blockIdx.y * 64;     // N tile
    const int l0     = tile * 32;

    // Stage gather indices (32 l-values x 16 k), clamped for the tail tile
    int* sIdx = (int*)(sm + SM_IDX);
#pragma unroll
    for (int e = tid; e < 512; e += NTHREADS) {
        int li = e >> 4, kk = e & 15;
        int l = l0 + li;
        if (l > LL - 1) l = LL - 1;
        sIdx[e] = idx[l * KK + kk];
    }
    __syncthreads();

    // 64x32 warp tile: acc[am 0..3][nn 0..3][4] = 64 regs
    float acc[4][4][4];
#pragma unroll
    for (int a = 0; a < 4; a++)
#pragma unroll
        for (int n = 0; n < 4; n++)
#pragma unroll
            for (int q = 0; q < 4; q++) acc[a][n][q] = 0.f;

    issue_chunk(0, sb + SM_STAGE + 0 * STAGE_BYTES, sIdx, n0, tid);
    CP_COMMIT();
    issue_chunk(1, sb + SM_STAGE + 1 * STAGE_BYTES, sIdx, n0, tid);
    CP_COMMIT();

    // Per-lane ldmatrix address invariants
    const int rA        = warp_m * 64 + (lane & 15);      // am adds +16 rows (row&7 invariant)
    const uint32_t aRow = (uint32_t)rA * 128u;
    const uint32_t aPh  = (uint32_t)((rA & 7) << 4);
    const int colAh     = (lane >> 4) * 16;
    const int rBb       = warp_n * 32 + (lane & 7) + ((lane >> 4) << 3);  // nb adds +16 rows
    const uint32_t bPh  = (uint32_t)((lane & 7) << 4);
    const int colBh     = ((lane >> 3) & 1) * 16;

    for (int c = 0; c < 64; c++) {
        CP_WAIT1();
        __syncthreads();

        const uint32_t Ab = sb + SM_STAGE + (c % 3) * STAGE_BYTES;
        const uint32_t Bb = Ab + A_BYTES;

        // ---- all B fragments of the chunk (8 LDSM, 32 regs) ----
        uint32_t b[4][2][4];
#pragma unroll
        for (int ks = 0; ks < 4; ks++) {
            const uint32_t offB = (uint32_t)(ks * 32 + colBh) ^ bPh;
#pragma unroll
            for (int nb = 0; nb < 2; nb++) {
                ldmx4(b[ks][nb][0], b[ks][nb][1], b[ks][nb][2], b[ks][nb][3],
                      Bb + (uint32_t)(rBb + nb * 16) * 128u + offB);
            }
        }

        // ---- A fragments for ks=0 ----
        uint32_t a[2][4][4];
        {
            const uint32_t offA = (uint32_t)(colAh) ^ aPh;
#pragma unroll
            for (int am = 0; am < 4; am++)
                ldmx4(a[0][am][0], a[0][am][1], a[0][am][2], a[0][am][3],
                      Ab + aRow + (uint32_t)am * 2048u + offA);
        }

        // ---- issue next chunk's loads while LDSMs are in flight ----
        if (c + 2 < 64)
            issue_chunk(c + 2, sb + SM_STAGE + ((c + 2) % 3) * STAGE_BYTES, sIdx, n0, tid);
        CP_COMMIT();

        // ---- ks loop: prefetch A(ks+1), then MMA(ks) ----
#pragma unroll
        for (int ks = 0; ks < 4; ks++) {
            const int cur = ks & 1;
            const int nxt = cur ^ 1;
            if (ks < 3) {
                const uint32_t offA = (uint32_t)((ks + 1) * 32 + colAh) ^ aPh;
#pragma unroll
                for (int am = 0; am < 4; am++)
                    ldmx4(a[nxt][am][0], a[nxt][am][1], a[nxt][am][2], a[nxt][am][3],
                          Ab + aRow + (uint32_t)am * 2048u + offA);
            }
#pragma unroll
            for (int am = 0; am < 4; am++) {
#pragma unroll
                for (int nb = 0; nb < 2; nb++) {
                    mma16816(acc[am][nb * 2 + 0], a[cur][am], b[ks][nb][0], b[ks][nb][1]);
                    mma16816(acc[am][nb * 2 + 1], a[cur][am], b[ks][nb][2], b[ks][nb][3]);
                }
            }
        }
    }

    // ---- Epilogue: bias add + store (row m -> b = m&3, l = m>>2) ----
    const bool tail = (tile == MTILES - 1);
#pragma unroll
    for (int am = 0; am < 4; am++) {
#pragma unroll
        for (int nn = 0; nn < 4; nn++) {
            const int o = n0 + warp_n * 32 + nn * 8 + (lane & 3) * 2;
            const float2 bz = *(const float2*)&bias[o];
            const int m = tile * 128 + warp_m * 64 + am * 16 + (lane >> 2);
            if (!tail || m < MTOT) {
                float2 v;
                v.x = acc[am][nn][0] + bz.x;
                v.y = acc[am][nn][1] + bz.y;
                *(float2*)&out[((size_t)(m & 3) * LL + (m >> 2)) * OO + o] = v;
            }
            const int m2 = m + 8;
            if (!tail || m2 < MTOT) {
                float2 v;
                v.x = acc[am][nn][2] + bz.x;
                v.y = acc[am][nn][3] + bz.y;
                *(float2*)&out[((size_t)(m2 & 3) * LL + (m2 >> 2)) * OO + o] = v;
            }
        }
    }
}

// ---------------- launch ----------------
extern "C" void kernel_launch(void* const* d_in, const int* in_sizes, int n_in,
                              void* d_out, int out_size) {
    const float* x    = (const float*)d_in[0];   // (4, 10000, 256) fp32
    const int*   idx  = (const int*)d_in[1];     // (10000, 16) int32
    const float* mask = (const float*)d_in[2];   // (16, 256, 256) fp32
    const float* bias = (const float*)d_in[3];   // (256,) fp32
    float*       out  = (float*)d_out;           // (4, 10000, 256) fp32

    (void)in_sizes; (void)n_in; (void)out_size;

    static bool attr_set = false;
    if (!attr_set) {
        cudaFuncSetAttribute(piconv_mma_kernel,
                             cudaFuncAttributeMaxDynamicSharedMemorySize, DYN_SMEM);
        attr_set = true;
    }

    prologue_kernel<<<3524, 1024>>>(x, mask);
    piconv_mma_kernel<<<dim3(MTILES, 4), NTHREADS, DYN_SMEM>>>(idx, bias, out);
}

// round 15
// speedup vs baseline: 2.4229x; 1.1743x over previous
#include <cuda_runtime.h>
#include <cuda_fp16.h>
#include <stdint.h>

// ---------------- problem constants ----------------
#define BB 4
#define LL 10000
#define KK 16
#define II 256
#define OO 256
#define MTOT (BB * LL)          // 40000
#define MTILES 313              // ceil(40000 / 128)

// ---------------- device scratch ----------------
__device__ __align__(16) __half g_xh[(size_t)BB * LL * II];     // x in fp16
__device__ __align__(16) __half g_maskT[(size_t)KK * OO * II];  // mask transposed: [k][o][i]

// ---------------- helpers ----------------
__device__ __forceinline__ uint32_t smem_to_u32(const void* p) {
    uint32_t a;
    asm("{ .reg .u64 t; cvta.to.shared.u64 t, %1; cvt.u32.u64 %0, t; }"
        : "=r"(a) : "l"(p));
    return a;
}
__device__ __forceinline__ void cp_async16(uint32_t dst, const void* src) {
    asm volatile("cp.async.cg.shared.global [%0], [%1], 16;" :: "r"(dst), "l"(src));
}
#define CP_COMMIT() asm volatile("cp.async.commit_group;" ::: "memory")
#define CP_WAIT1()  asm volatile("cp.async.wait_group 1;" ::: "memory")

__device__ __forceinline__ void ldmx4(uint32_t& r0, uint32_t& r1, uint32_t& r2, uint32_t& r3,
                                      uint32_t addr) {
    asm volatile("ldmatrix.sync.aligned.m8n8.x4.shared.b16 {%0,%1,%2,%3}, [%4];"
                 : "=r"(r0), "=r"(r1), "=r"(r2), "=r"(r3) : "r"(addr));
}
__device__ __forceinline__ void mma16816(float* c, const uint32_t* a, uint32_t b0, uint32_t b1) {
    asm volatile(
        "mma.sync.aligned.m16n8k16.row.col.f32.f16.f16.f32 "
        "{%0,%1,%2,%3}, {%4,%5,%6,%7}, {%8,%9}, {%0,%1,%2,%3};"
        : "+f"(c[0]), "+f"(c[1]), "+f"(c[2]), "+f"(c[3])
        : "r"(a[0]), "r"(a[1]), "r"(a[2]), "r"(a[3]), "r"(b0), "r"(b1));
}

// ---------------- merged prologue ----------------
__global__ void __launch_bounds__(1024)
prologue_kernel(const float* __restrict__ x, const float* __restrict__ mask) {
    if (blockIdx.x < 2500) {
        int t = blockIdx.x * 1024 + threadIdx.x;
        float4 v = ((const float4*)x)[t];
        __half2* dst = ((__half2*)g_xh) + 2 * t;
        dst[0] = __floats2half2_rn(v.x, v.y);
        dst[1] = __floats2half2_rn(v.z, v.w);
    } else {
        __shared__ float ts[32][33];
        int bb  = blockIdx.x - 2500;         // 0..1023
        int k   = bb >> 6;                   // 16 experts
        int rem = bb & 63;
        int i0  = (rem >> 3) * 32;
        int o0  = (rem & 7) * 32;
        int tx  = threadIdx.x & 31;
        int ty  = threadIdx.x >> 5;
        ts[ty][tx] = mask[((size_t)k * II + (i0 + ty)) * OO + o0 + tx];
        __syncthreads();
        g_maskT[((size_t)k * OO + (o0 + ty)) * II + i0 + tx] = __float2half(ts[tx][ty]);
    }
}

// ---------------- main kernel ----------------
// R9 config: CTA 128(M)x64(N), 4 warps 2(M)x2(N) 64x32 tiles, 3-stage lockstep
// cp.async pipeline, 3 CTAs/SM, grid (313,4) = 2.82/3 waves.
// NEW: all loader address math hoisted — per-thread gather pointers pa[8]
// refreshed once per 4-chunk expert group, constant-immediate dst offsets,
// rolling stage bases. Consume body identical to R9.
#define SM_IDX   0
#define SM_STAGE 2048
#define STAGE_BYTES 24576
#define A_BYTES  16384
#define DYN_SMEM (SM_STAGE + 3 * STAGE_BYTES)   // 75776
#define NTHREADS 128

// Issue the 12 cp.async of one chunk. IO = ibase byte offset (compile-time).
#define ISSUE_CHUNK(IO) do {                                                  \
    const uint32_t _dA = dIss + preOff;                                       \
    const uint32_t _dB = _dA + A_BYTES;                                       \
    _Pragma("unroll")                                                         \
    for (int _j = 0; _j < 8; _j++)                                            \
        cp_async16(_dA + _j * 2048, pa[_j] + (IO));                           \
    _Pragma("unroll")                                                         \
    for (int _j = 0; _j < 4; _j++)                                            \
        cp_async16(_dB + _j * 2048, pb + (IO) + _j * 8192);                   \
    dIss = (dIss == dHi) ? dLo : dIss + STAGE_BYTES;                          \
} while (0)

__global__ void __launch_bounds__(NTHREADS, 3)
piconv_mma_kernel(const int* __restrict__ idx,
                  const float* __restrict__ bias,
                  float* __restrict__ out) {
    extern __shared__ char sm[];
    const uint32_t sb = smem_to_u32(sm);
    const int tid    = threadIdx.x;
    const int lane   = tid & 31;
    const int wid    = tid >> 5;
    const int warp_m = wid >> 1;            // 0..1  (64 rows each)
    const int warp_n = wid & 1;             // 0..1  (32 cols each)
    const int tile   = blockIdx.x;          // M tile (128 rows)
    const int n0     = blockIdx.y * 64;     // N tile
    const int l0     = tile * 32;

    // Stage gather indices (32 l-values x 16 k), clamped for the tail tile
    int* sIdx = (int*)(sm + SM_IDX);
#pragma unroll
    for (int e = tid; e < 512; e += NTHREADS) {
        int li = e >> 4, kk = e & 15;
        int l = l0 + li;
        if (l > LL - 1) l = LL - 1;
        sIdx[e] = idx[l * KK + kk];
    }
    __syncthreads();

    // 64x32 warp tile: acc[am 0..3][nn 0..3][4] = 64 regs
    float acc[4][4][4];
#pragma unroll
    for (int a = 0; a < 4; a++)
#pragma unroll
        for (int n = 0; n < 4; n++)
#pragma unroll
            for (int q = 0; q < 4; q++) acc[a][n][q] = 0.f;

    // ---- loader invariants (per thread) ----
    // op id s = tid + 128*j  ->  row = (tid>>3) + 16*j, seg = tid&7
    const int rowBase = tid >> 3;                 // 0..15
    const int segOff  = (tid & 7) * 16;           // bytes within row
    const uint32_t ph = (uint32_t)((rowBase & 7) << 4);
    const uint32_t preOff = ((uint32_t)(rowBase * 128 + segOff)) ^ ph;  // + j*2048 per op
    const int liBase = rowBase >> 2;              // li_j = liBase + 4*j (== wid: warp-broadcast LDS)
    const int bpart  = rowBase & 3;
    const char* const xbase = (const char*)g_xh + ((size_t)bpart * LL) * 512 + segOff;
    const char* pb = (const char*)g_maskT + ((size_t)(n0 + rowBase)) * 512 + segOff; // + kexp*131072

    // gather pointers for the current-issue expert group
    const char* pa[8];
#pragma unroll
    for (int j = 0; j < 8; j++)
        pa[j] = xbase + (size_t)sIdx[(liBase + 4 * j) * 16 + 0] * 512;

    // rolling stage bases
    const uint32_t dLo = sb + SM_STAGE;
    const uint32_t dHi = sb + SM_STAGE + 2 * STAGE_BYTES;
    uint32_t dIss = dLo;                          // stage of next issued chunk
    uint32_t dCon = dLo;                          // stage of next consumed chunk

    ISSUE_CHUNK(0);    CP_COMMIT();               // chunk 0 (kexp 0, ibase 0)
    ISSUE_CHUNK(128);  CP_COMMIT();               // chunk 1

    // Per-lane ldmatrix address invariants (R9)
    const int rA        = warp_m * 64 + (lane & 15);
    const uint32_t aRow = (uint32_t)rA * 128u;
    const uint32_t aPh  = (uint32_t)((rA & 7) << 4);
    const int colAh     = (lane >> 4) * 16;
    const int rBb       = warp_n * 32 + (lane & 7) + ((lane >> 4) << 3);
    const uint32_t bPh  = (uint32_t)((lane & 7) << 4);
    const int colBh     = ((lane >> 3) & 1) * 16;

    for (int c0 = 0; c0 < 64; c0 += 4) {          // one expert group per iteration
        const int kn = (c0 >> 2) + 1;             // next group's expert
#pragma unroll
        for (int ib = 0; ib < 4; ib++) {
            CP_WAIT1();
            __syncthreads();

            // ---- issue chunk c0+ib+2 ----
            if (ib == 0) {
                ISSUE_CHUNK(256);                 // (kexp, ibase 2)
            } else if (ib == 1) {
                ISSUE_CHUNK(384);                 // (kexp, ibase 3)
            } else {
                if (ib == 2 && c0 < 60) {
#pragma unroll
                    for (int j = 0; j < 8; j++)
                        pa[j] = xbase + (size_t)sIdx[(liBase + 4 * j) * 16 + kn] * 512;
                    pb += 131072;
                }
                if (c0 < 60) {
                    if (ib == 2) ISSUE_CHUNK(0);  // (kexp+1, ibase 0)
                    else         ISSUE_CHUNK(128);
                }
            }
            CP_COMMIT();                          // unconditional: keeps group count aligned

            // ---- consume chunk c0+ib (R9 body, verbatim) ----
            const uint32_t Ab = dCon;
            const uint32_t Bb = dCon + A_BYTES;
#pragma unroll
            for (int ks = 0; ks < 4; ks++) {
                uint32_t a[4][4];
                const uint32_t offA = (uint32_t)(ks * 32 + colAh) ^ aPh;
#pragma unroll
                for (int am = 0; am < 4; am++)
                    ldmx4(a[am][0], a[am][1], a[am][2], a[am][3],
                          Ab + aRow + (uint32_t)am * 2048u + offA);

                const uint32_t offB = (uint32_t)(ks * 32 + colBh) ^ bPh;
                uint32_t b[2][4];
#pragma unroll
                for (int nb = 0; nb < 2; nb++) {
                    ldmx4(b[nb][0], b[nb][1], b[nb][2], b[nb][3],
                          Bb + (uint32_t)(rBb + nb * 16) * 128u + offB);
                }
#pragma unroll
                for (int am = 0; am < 4; am++) {
#pragma unroll
                    for (int nb = 0; nb < 2; nb++) {
                        mma16816(acc[am][nb * 2 + 0], a[am], b[nb][0], b[nb][1]);
                        mma16816(acc[am][nb * 2 + 1], a[am], b[nb][2], b[nb][3]);
                    }
                }
            }
            dCon = (dCon == dHi) ? dLo : dCon + STAGE_BYTES;
        }
    }

    // ---- Epilogue: bias add + store (row m -> b = m&3, l = m>>2) ----
    const bool tail = (tile == MTILES - 1);
#pragma unroll
    for (int am = 0; am < 4; am++) {
#pragma unroll
        for (int nn = 0; nn < 4; nn++) {
            const int o = n0 + warp_n * 32 + nn * 8 + (lane & 3) * 2;
            const float2 bz = *(const float2*)&bias[o];
            const int m = tile * 128 + warp_m * 64 + am * 16 + (lane >> 2);
            if (!tail || m < MTOT) {
                float2 v;
                v.x = acc[am][nn][0] + bz.x;
                v.y = acc[am][nn][1] + bz.y;
                *(float2*)&out[((size_t)(m & 3) * LL + (m >> 2)) * OO + o] = v;
            }
            const int m2 = m + 8;
            if (!tail || m2 < MTOT) {
                float2 v;
                v.x = acc[am][nn][2] + bz.x;
                v.y = acc[am][nn][3] + bz.y;
                *(float2*)&out[((size_t)(m2 & 3) * LL + (m2 >> 2)) * OO + o] = v;
            }
        }
    }
}

// ---------------- launch ----------------
extern "C" void kernel_launch(void* const* d_in, const int* in_sizes, int n_in,
                              void* d_out, int out_size) {
    const float* x    = (const float*)d_in[0];   // (4, 10000, 256) fp32
    const int*   idx  = (const int*)d_in[1];     // (10000, 16) int32
    const float* mask = (const float*)d_in[2];   // (16, 256, 256) fp32
    const float* bias = (const float*)d_in[3];   // (256,) fp32
    float*       out  = (float*)d_out;           // (4, 10000, 256) fp32

    (void)in_sizes; (void)n_in; (void)out_size;

    static bool attr_set = false;
    if (!attr_set) {
        cudaFuncSetAttribute(piconv_mma_kernel,
                             cudaFuncAttributeMaxDynamicSharedMemorySize, DYN_SMEM);
        attr_set = true;
    }

    prologue_kernel<<<3524, 1024>>>(x, mask);
    piconv_mma_kernel<<<dim3(MTILES, 4), NTHREADS, DYN_SMEM>>>(idx, bias, out);
}

// round 16
// speedup vs baseline: 2.4301x; 1.0030x over previous
#include <cuda_runtime.h>
#include <cuda_fp16.h>
#include <stdint.h>

// ---------------- problem constants ----------------
#define BB 4
#define LL 10000
#define KK 16
#define II 256
#define OO 256
#define MTOT (BB * LL)          // 40000
#define MTILES 313              // ceil(40000 / 128)

// ---------------- device scratch ----------------
__device__ __align__(16) __half g_xh[(size_t)BB * LL * II];     // x in fp16
__device__ __align__(16) __half g_maskT[(size_t)KK * OO * II];  // mask transposed: [k][o][i]

// ---------------- helpers ----------------
__device__ __forceinline__ uint32_t smem_to_u32(const void* p) {
    uint32_t a;
    asm("{ .reg .u64 t; cvta.to.shared.u64 t, %1; cvt.u32.u64 %0, t; }"
        : "=r"(a) : "l"(p));
    return a;
}
__device__ __forceinline__ void cp_async16(uint32_t dst, const void* src) {
    asm volatile("cp.async.cg.shared.global [%0], [%1], 16;" :: "r"(dst), "l"(src));
}
#define CP_COMMIT() asm volatile("cp.async.commit_group;" ::: "memory")
#define CP_WAIT1()  asm volatile("cp.async.wait_group 1;" ::: "memory")

__device__ __forceinline__ void ldmx4(uint32_t& r0, uint32_t& r1, uint32_t& r2, uint32_t& r3,
                                      uint32_t addr) {
    asm volatile("ldmatrix.sync.aligned.m8n8.x4.shared.b16 {%0,%1,%2,%3}, [%4];"
                 : "=r"(r0), "=r"(r1), "=r"(r2), "=r"(r3) : "r"(addr));
}
__device__ __forceinline__ void mma16816(float* c, const uint32_t* a, uint32_t b0, uint32_t b1) {
    asm volatile(
        "mma.sync.aligned.m16n8k16.row.col.f32.f16.f16.f32 "
        "{%0,%1,%2,%3}, {%4,%5,%6,%7}, {%8,%9}, {%0,%1,%2,%3};"
        : "+f"(c[0]), "+f"(c[1]), "+f"(c[2]), "+f"(c[3])
        : "r"(a[0]), "r"(a[1]), "r"(a[2]), "r"(a[3]), "r"(b0), "r"(b1));
}

// ---------------- prologue 1: x fp32 -> fp16 (MLP=4, fused 8B stores) ----------------
__global__ void __launch_bounds__(256)
convert_x_kernel(const float* __restrict__ x) {
    const int t = blockIdx.x * 256 + threadIdx.x;     // 640000 threads
    const float4* src = (const float4*)x;             // 2,560,000 float4
    uint2* dst = (uint2*)g_xh;
#pragma unroll
    for (int i = 0; i < 4; i++) {
        const int p = t + i * 640000;
        float4 v = src[p];
        __half2 h0 = __floats2half2_rn(v.x, v.y);
        __half2 h1 = __floats2half2_rn(v.z, v.w);
        uint2 u;
        u.x = *reinterpret_cast<uint32_t*>(&h0);
        u.y = *reinterpret_cast<uint32_t*>(&h1);
        dst[p] = u;
    }
}

// ---------------- prologue 2: mask[k][i][o] -> maskT[k][o][i] fp16 ----------------
__global__ void __launch_bounds__(1024)
transpose_mask_kernel(const float* __restrict__ mask) {
    __shared__ float ts[32][33];
    int bb  = blockIdx.x;                // 0..1023
    int k   = bb >> 6;                   // 16 experts
    int rem = bb & 63;
    int i0  = (rem >> 3) * 32;
    int o0  = (rem & 7) * 32;
    int tx  = threadIdx.x & 31;
    int ty  = threadIdx.x >> 5;
    ts[ty][tx] = mask[((size_t)k * II + (i0 + ty)) * OO + o0 + tx];
    __syncthreads();
    g_maskT[((size_t)k * OO + (o0 + ty)) * II + i0 + tx] = __float2half(ts[tx][ty]);
}

// ---------------- main kernel (R15, unchanged) ----------------
// R9 config: CTA 128(M)x64(N), 4 warps 2(M)x2(N) 64x32 tiles, 3-stage lockstep
// cp.async pipeline, 3 CTAs/SM, grid (313,4) = 2.82/3 waves.
// Loader address math fully hoisted (per-thread gather pointers pa[8] refreshed
// once per 4-chunk expert group, constant-immediate dst offsets, rolling bases).
#define SM_IDX   0
#define SM_STAGE 2048
#define STAGE_BYTES 24576
#define A_BYTES  16384
#define DYN_SMEM (SM_STAGE + 3 * STAGE_BYTES)   // 75776
#define NTHREADS 128

// Issue the 12 cp.async of one chunk. IO = ibase byte offset (compile-time).
#define ISSUE_CHUNK(IO) do {                                                  \
    const uint32_t _dA = dIss + preOff;                                       \
    const uint32_t _dB = _dA + A_BYTES;                                       \
    _Pragma("unroll")                                                         \
    for (int _j = 0; _j < 8; _j++)                                            \
        cp_async16(_dA + _j * 2048, pa[_j] + (IO));                           \
    _Pragma("unroll")                                                         \
    for (int _j = 0; _j < 4; _j++)                                            \
        cp_async16(_dB + _j * 2048, pb + (IO) + _j * 8192);                   \
    dIss = (dIss == dHi) ? dLo : dIss + STAGE_BYTES;                          \
} while (0)

__global__ void __launch_bounds__(NTHREADS, 3)
piconv_mma_kernel(const int* __restrict__ idx,
                  const float* __restrict__ bias,
                  float* __restrict__ out) {
    extern __shared__ char sm[];
    const uint32_t sb = smem_to_u32(sm);
    const int tid    = threadIdx.x;
    const int lane   = tid & 31;
    const int wid    = tid >> 5;
    const int warp_m = wid >> 1;            // 0..1  (64 rows each)
    const int warp_n = wid & 1;             // 0..1  (32 cols each)
    const int tile   = blockIdx.x;          // M tile (128 rows)
    const int n0     = blockIdx.y * 64;     // N tile
    const int l0     = tile * 32;

    // Stage gather indices (32 l-values x 16 k), clamped for the tail tile
    int* sIdx = (int*)(sm + SM_IDX);
#pragma unroll
    for (int e = tid; e < 512; e += NTHREADS) {
        int li = e >> 4, kk = e & 15;
        int l = l0 + li;
        if (l > LL - 1) l = LL - 1;
        sIdx[e] = idx[l * KK + kk];
    }
    __syncthreads();

    // 64x32 warp tile: acc[am 0..3][nn 0..3][4] = 64 regs
    float acc[4][4][4];
#pragma unroll
    for (int a = 0; a < 4; a++)
#pragma unroll
        for (int n = 0; n < 4; n++)
#pragma unroll
            for (int q = 0; q < 4; q++) acc[a][n][q] = 0.f;

    // ---- loader invariants (per thread) ----
    const int rowBase = tid >> 3;                 // 0..15
    const int segOff  = (tid & 7) * 16;           // bytes within row
    const uint32_t ph = (uint32_t)((rowBase & 7) << 4);
    const uint32_t preOff = ((uint32_t)(rowBase * 128 + segOff)) ^ ph;  // + j*2048 per op
    const int liBase = rowBase >> 2;
    const int bpart  = rowBase & 3;
    const char* const xbase = (const char*)g_xh + ((size_t)bpart * LL) * 512 + segOff;
    const char* pb = (const char*)g_maskT + ((size_t)(n0 + rowBase)) * 512 + segOff; // + kexp*131072

    // gather pointers for the current-issue expert group
    const char* pa[8];
#pragma unroll
    for (int j = 0; j < 8; j++)
        pa[j] = xbase + (size_t)sIdx[(liBase + 4 * j) * 16 + 0] * 512;

    // rolling stage bases
    const uint32_t dLo = sb + SM_STAGE;
    const uint32_t dHi = sb + SM_STAGE + 2 * STAGE_BYTES;
    uint32_t dIss = dLo;                          // stage of next issued chunk
    uint32_t dCon = dLo;                          // stage of next consumed chunk

    ISSUE_CHUNK(0);    CP_COMMIT();               // chunk 0 (kexp 0, ibase 0)
    ISSUE_CHUNK(128);  CP_COMMIT();               // chunk 1

    // Per-lane ldmatrix address invariants
    const int rA        = warp_m * 64 + (lane & 15);
    const uint32_t aRow = (uint32_t)rA * 128u;
    const uint32_t aPh  = (uint32_t)((rA & 7) << 4);
    const int colAh     = (lane >> 4) * 16;
    const int rBb       = warp_n * 32 + (lane & 7) + ((lane >> 4) << 3);
    const uint32_t bPh  = (uint32_t)((lane & 7) << 4);
    const int colBh     = ((lane >> 3) & 1) * 16;

    for (int c0 = 0; c0 < 64; c0 += 4) {          // one expert group per iteration
        const int kn = (c0 >> 2) + 1;             // next group's expert
#pragma unroll
        for (int ib = 0; ib < 4; ib++) {
            CP_WAIT1();
            __syncthreads();

            // ---- issue chunk c0+ib+2 ----
            if (ib == 0) {
                ISSUE_CHUNK(256);                 // (kexp, ibase 2)
            } else if (ib == 1) {
                ISSUE_CHUNK(384);                 // (kexp, ibase 3)
            } else {
                if (ib == 2 && c0 < 60) {
#pragma unroll
                    for (int j = 0; j < 8; j++)
                        pa[j] = xbase + (size_t)sIdx[(liBase + 4 * j) * 16 + kn] * 512;
                    pb += 131072;
                }
                if (c0 < 60) {
                    if (ib == 2) ISSUE_CHUNK(0);  // (kexp+1, ibase 0)
                    else         ISSUE_CHUNK(128);
                }
            }
            CP_COMMIT();                          // unconditional: keeps group count aligned

            // ---- consume chunk c0+ib ----
            const uint32_t Ab = dCon;
            const uint32_t Bb = dCon + A_BYTES;
#pragma unroll
            for (int ks = 0; ks < 4; ks++) {
                uint32_t a[4][4];
                const uint32_t offA = (uint32_t)(ks * 32 + colAh) ^ aPh;
#pragma unroll
                for (int am = 0; am < 4; am++)
                    ldmx4(a[am][0], a[am][1], a[am][2], a[am][3],
                          Ab + aRow + (uint32_t)am * 2048u + offA);

                const uint32_t offB = (uint32_t)(ks * 32 + colBh) ^ bPh;
                uint32_t b[2][4];
#pragma unroll
                for (int nb = 0; nb < 2; nb++) {
                    ldmx4(b[nb][0], b[nb][1], b[nb][2], b[nb][3],
                          Bb + (uint32_t)(rBb + nb * 16) * 128u + offB);
                }
#pragma unroll
                for (int am = 0; am < 4; am++) {
#pragma unroll
                    for (int nb = 0; nb < 2; nb++) {
                        mma16816(acc[am][nb * 2 + 0], a[am], b[nb][0], b[nb][1]);
                        mma16816(acc[am][nb * 2 + 1], a[am], b[nb][2], b[nb][3]);
                    }
                }
            }
            dCon = (dCon == dHi) ? dLo : dCon + STAGE_BYTES;
        }
    }

    // ---- Epilogue: bias add + store (row m -> b = m&3, l = m>>2) ----
    const bool tail = (tile == MTILES - 1);
#pragma unroll
    for (int am = 0; am < 4; am++) {
#pragma unroll
        for (int nn = 0; nn < 4; nn++) {
            const int o = n0 + warp_n * 32 + nn * 8 + (lane & 3) * 2;
            const float2 bz = *(const float2*)&bias[o];
            const int m = tile * 128 + warp_m * 64 + am * 16 + (lane >> 2);
            if (!tail || m < MTOT) {
                float2 v;
                v.x = acc[am][nn][0] + bz.x;
                v.y = acc[am][nn][1] + bz.y;
                *(float2*)&out[((size_t)(m & 3) * LL + (m >> 2)) * OO + o] = v;
            }
            const int m2 = m + 8;
            if (!tail || m2 < MTOT) {
                float2 v;
                v.x = acc[am][nn][2] + bz.x;
                v.y = acc[am][nn][3] + bz.y;
                *(float2*)&out[((size_t)(m2 & 3) * LL + (m2 >> 2)) * OO + o] = v;
            }
        }
    }
}

// ---------------- launch ----------------
extern "C" void kernel_launch(void* const* d_in, const int* in_sizes, int n_in,
                              void* d_out, int out_size) {
    const float* x    = (const float*)d_in[0];   // (4, 10000, 256) fp32
    const int*   idx  = (const int*)d_in[1];     // (10000, 16) int32
    const float* mask = (const float*)d_in[2];   // (16, 256, 256) fp32
    const float* bias = (const float*)d_in[3];   // (256,) fp32
    float*       out  = (float*)d_out;           // (4, 10000, 256) fp32

    (void)in_sizes; (void)n_in; (void)out_size;

    static bool attr_set = false;
    if (!attr_set) {
        cudaFuncSetAttribute(piconv_mma_kernel,
                             cudaFuncAttributeMaxDynamicSharedMemorySize, DYN_SMEM);
        attr_set = true;
    }

    convert_x_kernel<<<2500, 256>>>(x);
    transpose_mask_kernel<<<1024, 1024>>>(mask);
    piconv_mma_kernel<<<dim3(MTILES, 4), NTHREADS, DYN_SMEM>>>(idx, bias, out);
}

// round 17
// speedup vs baseline: 2.4849x; 1.0225x over previous
#include <cuda_runtime.h>
#include <cuda_fp16.h>
#include <stdint.h>

// ---------------- problem constants ----------------
#define BB 4
#define LL 10000
#define KK 16
#define II 256
#define OO 256
#define MTOT (BB * LL)          // 40000
#define MTILES 313              // ceil(40000 / 128)

// ---------------- device scratch ----------------
__device__ __align__(16) __half g_xh[(size_t)BB * LL * II];     // x in fp16
__device__ __align__(16) __half g_maskT[(size_t)KK * OO * II];  // mask transposed: [k][o][i]

// ---------------- helpers ----------------
__device__ __forceinline__ uint32_t smem_to_u32(const void* p) {
    uint32_t a;
    asm("{ .reg .u64 t; cvta.to.shared.u64 t, %1; cvt.u32.u64 %0, t; }"
        : "=r"(a) : "l"(p));
    return a;
}
__device__ __forceinline__ void cp_async16(uint32_t dst, const void* src) {
    asm volatile("cp.async.cg.shared.global [%0], [%1], 16;" :: "r"(dst), "l"(src));
}
#define CP_COMMIT() asm volatile("cp.async.commit_group;" ::: "memory")
#define CP_WAIT1()  asm volatile("cp.async.wait_group 1;" ::: "memory")

__device__ __forceinline__ void ldmx4(uint32_t& r0, uint32_t& r1, uint32_t& r2, uint32_t& r3,
                                      uint32_t addr) {
    asm volatile("ldmatrix.sync.aligned.m8n8.x4.shared.b16 {%0,%1,%2,%3}, [%4];"
                 : "=r"(r0), "=r"(r1), "=r"(r2), "=r"(r3) : "r"(addr));
}
__device__ __forceinline__ void mma16816(float* c, const uint32_t* a, uint32_t b0, uint32_t b1) {
    asm volatile(
        "mma.sync.aligned.m16n8k16.row.col.f32.f16.f16.f32 "
        "{%0,%1,%2,%3}, {%4,%5,%6,%7}, {%8,%9}, {%0,%1,%2,%3};"
        : "+f"(c[0]), "+f"(c[1]), "+f"(c[2]), "+f"(c[3])
        : "r"(a[0]), "r"(a[1]), "r"(a[2]), "r"(a[3]), "r"(b0), "r"(b1));
}

// ---------------- merged prologue (one launch) ----------------
// blocks [0, 1250):   x fp32 -> fp16, MLP=8 (256 thr x 8 float4)
// blocks [1250, 2274): mask[k][i][o] -> maskT[k][o][i] fp16 (32x32 tiles, 256 thr)
__global__ void __launch_bounds__(256)
prologue_kernel(const float* __restrict__ x, const float* __restrict__ mask) {
    if (blockIdx.x < 1250) {
        const int t = blockIdx.x * 256 + threadIdx.x;   // 320000 threads
        const float4* src = (const float4*)x;           // 2,560,000 float4
        uint2* dst = (uint2*)g_xh;
#pragma unroll
        for (int i = 0; i < 8; i++) {
            const int p = t + i * 320000;
            float4 v = src[p];
            __half2 h0 = __floats2half2_rn(v.x, v.y);
            __half2 h1 = __floats2half2_rn(v.z, v.w);
            uint2 u;
            u.x = *reinterpret_cast<uint32_t*>(&h0);
            u.y = *reinterpret_cast<uint32_t*>(&h1);
            dst[p] = u;
        }
    } else {
        __shared__ float ts[32][33];
        int bb  = blockIdx.x - 1250;         // 0..1023
        int k   = bb >> 6;                   // 16 experts
        int rem = bb & 63;
        int i0  = (rem >> 3) * 32;
        int o0  = (rem & 7) * 32;
        int tx  = threadIdx.x & 31;
        int ty8 = threadIdx.x >> 5;          // 0..7
#pragma unroll
        for (int r = 0; r < 4; r++) {
            int row = ty8 + r * 8;
            ts[row][tx] = mask[((size_t)k * II + (i0 + row)) * OO + o0 + tx];
        }
        __syncthreads();
#pragma unroll
        for (int r = 0; r < 4; r++) {
            int ow = ty8 + r * 8;
            g_maskT[((size_t)k * OO + (o0 + ow)) * II + i0 + tx] = __float2half(ts[tx][ow]);
        }
    }
}

// ---------------- main kernel (R15, byte-identical) ----------------
// CTA 128(M)x64(N), 4 warps 2(M)x2(N) 64x32 tiles, 3-stage lockstep cp.async
// pipeline, 3 CTAs/SM, grid (313,4) = 2.82/3 waves. Loader address math fully
// hoisted (pa[8] refreshed once per 4-chunk expert group, rolling stage bases).
#define SM_IDX   0
#define SM_STAGE 2048
#define STAGE_BYTES 24576
#define A_BYTES  16384
#define DYN_SMEM (SM_STAGE + 3 * STAGE_BYTES)   // 75776
#define NTHREADS 128

// Issue the 12 cp.async of one chunk. IO = ibase byte offset (compile-time).
#define ISSUE_CHUNK(IO) do {                                                  \
    const uint32_t _dA = dIss + preOff;                                       \
    const uint32_t _dB = _dA + A_BYTES;                                       \
    _Pragma("unroll")                                                         \
    for (int _j = 0; _j < 8; _j++)                                            \
        cp_async16(_dA + _j * 2048, pa[_j] + (IO));                           \
    _Pragma("unroll")                                                         \
    for (int _j = 0; _j < 4; _j++)                                            \
        cp_async16(_dB + _j * 2048, pb + (IO) + _j * 8192);                   \
    dIss = (dIss == dHi) ? dLo : dIss + STAGE_BYTES;                          \
} while (0)

__global__ void __launch_bounds__(NTHREADS, 3)
piconv_mma_kernel(const int* __restrict__ idx,
                  const float* __restrict__ bias,
                  float* __restrict__ out) {
    extern __shared__ char sm[];
    const uint32_t sb = smem_to_u32(sm);
    const int tid    = threadIdx.x;
    const int lane   = tid & 31;
    const int wid    = tid >> 5;
    const int warp_m = wid >> 1;            // 0..1  (64 rows each)
    const int warp_n = wid & 1;             // 0..1  (32 cols each)
    const int tile   = blockIdx.x;          // M tile (128 rows)
    const int n0     = blockIdx.y * 64;     // N tile
    const int l0     = tile * 32;

    // Stage gather indices (32 l-values x 16 k), clamped for the tail tile
    int* sIdx = (int*)(sm + SM_IDX);
#pragma unroll
    for (int e = tid; e < 512; e += NTHREADS) {
        int li = e >> 4, kk = e & 15;
        int l = l0 + li;
        if (l > LL - 1) l = LL - 1;
        sIdx[e] = idx[l * KK + kk];
    }
    __syncthreads();

    // 64x32 warp tile: acc[am 0..3][nn 0..3][4] = 64 regs
    float acc[4][4][4];
#pragma unroll
    for (int a = 0; a < 4; a++)
#pragma unroll
        for (int n = 0; n < 4; n++)
#pragma unroll
            for (int q = 0; q < 4; q++) acc[a][n][q] = 0.f;

    // ---- loader invariants (per thread) ----
    const int rowBase = tid >> 3;                 // 0..15
    const int segOff  = (tid & 7) * 16;           // bytes within row
    const uint32_t ph = (uint32_t)((rowBase & 7) << 4);
    const uint32_t preOff = ((uint32_t)(rowBase * 128 + segOff)) ^ ph;  // + j*2048 per op
    const int liBase = rowBase >> 2;
    const int bpart  = rowBase & 3;
    const char* const xbase = (const char*)g_xh + ((size_t)bpart * LL) * 512 + segOff;
    const char* pb = (const char*)g_maskT + ((size_t)(n0 + rowBase)) * 512 + segOff; // + kexp*131072

    // gather pointers for the current-issue expert group
    const char* pa[8];
#pragma unroll
    for (int j = 0; j < 8; j++)
        pa[j] = xbase + (size_t)sIdx[(liBase + 4 * j) * 16 + 0] * 512;

    // rolling stage bases
    const uint32_t dLo = sb + SM_STAGE;
    const uint32_t dHi = sb + SM_STAGE + 2 * STAGE_BYTES;
    uint32_t dIss = dLo;                          // stage of next issued chunk
    uint32_t dCon = dLo;                          // stage of next consumed chunk

    ISSUE_CHUNK(0);    CP_COMMIT();               // chunk 0 (kexp 0, ibase 0)
    ISSUE_CHUNK(128);  CP_COMMIT();               // chunk 1

    // Per-lane ldmatrix address invariants
    const int rA        = warp_m * 64 + (lane & 15);
    const uint32_t aRow = (uint32_t)rA * 128u;
    const uint32_t aPh  = (uint32_t)((rA & 7) << 4);
    const int colAh     = (lane >> 4) * 16;
    const int rBb       = warp_n * 32 + (lane & 7) + ((lane >> 4) << 3);
    const uint32_t bPh  = (uint32_t)((lane & 7) << 4);
    const int colBh     = ((lane >> 3) & 1) * 16;

    for (int c0 = 0; c0 < 64; c0 += 4) {          // one expert group per iteration
        const int kn = (c0 >> 2) + 1;             // next group's expert
#pragma unroll
        for (int ib = 0; ib < 4; ib++) {
            CP_WAIT1();
            __syncthreads();

            // ---- issue chunk c0+ib+2 ----
            if (ib == 0) {
                ISSUE_CHUNK(256);                 // (kexp, ibase 2)
            } else if (ib == 1) {
                ISSUE_CHUNK(384);                 // (kexp, ibase 3)
            } else {
                if (ib == 2 && c0 < 60) {
#pragma unroll
                    for (int j = 0; j < 8; j++)
                        pa[j] = xbase + (size_t)sIdx[(liBase + 4 * j) * 16 + kn] * 512;
                    pb += 131072;
                }
                if (c0 < 60) {
                    if (ib == 2) ISSUE_CHUNK(0);  // (kexp+1, ibase 0)
                    else         ISSUE_CHUNK(128);
                }
            }
            CP_COMMIT();                          // unconditional: keeps group count aligned

            // ---- consume chunk c0+ib ----
            const uint32_t Ab = dCon;
            const uint32_t Bb = dCon + A_BYTES;
#pragma unroll
            for (int ks = 0; ks < 4; ks++) {
                uint32_t a[4][4];
                const uint32_t offA = (uint32_t)(ks * 32 + colAh) ^ aPh;
#pragma unroll
                for (int am = 0; am < 4; am++)
                    ldmx4(a[am][0], a[am][1], a[am][2], a[am][3],
                          Ab + aRow + (uint32_t)am * 2048u + offA);

                const uint32_t offB = (uint32_t)(ks * 32 + colBh) ^ bPh;
                uint32_t b[2][4];
#pragma unroll
                for (int nb = 0; nb < 2; nb++) {
                    ldmx4(b[nb][0], b[nb][1], b[nb][2], b[nb][3],
                          Bb + (uint32_t)(rBb + nb * 16) * 128u + offB);
                }
#pragma unroll
                for (int am = 0; am < 4; am++) {
#pragma unroll
                    for (int nb = 0; nb < 2; nb++) {
                        mma16816(acc[am][nb * 2 + 0], a[am], b[nb][0], b[nb][1]);
                        mma16816(acc[am][nb * 2 + 1], a[am], b[nb][2], b[nb][3]);
                    }
                }
            }
            dCon = (dCon == dHi) ? dLo : dCon + STAGE_BYTES;
        }
    }

    // ---- Epilogue: bias add + store (row m -> b = m&3, l = m>>2) ----
    const bool tail = (tile == MTILES - 1);
#pragma unroll
    for (int am = 0; am < 4; am++) {
#pragma unroll
        for (int nn = 0; nn < 4; nn++) {
            const int o = n0 + warp_n * 32 + nn * 8 + (lane & 3) * 2;
            const float2 bz = *(const float2*)&bias[o];
            const int m = tile * 128 + warp_m * 64 + am * 16 + (lane >> 2);
            if (!tail || m < MTOT) {
                float2 v;
                v.x = acc[am][nn][0] + bz.x;
                v.y = acc[am][nn][1] + bz.y;
                *(float2*)&out[((size_t)(m & 3) * LL + (m >> 2)) * OO + o] = v;
            }
            const int m2 = m + 8;
            if (!tail || m2 < MTOT) {
                float2 v;
                v.x = acc[am][nn][2] + bz.x;
                v.y = acc[am][nn][3] + bz.y;
                *(float2*)&out[((size_t)(m2 & 3) * LL + (m2 >> 2)) * OO + o] = v;
            }
        }
    }
}

// ---------------- launch ----------------
extern "C" void kernel_launch(void* const* d_in, const int* in_sizes, int n_in,
                              void* d_out, int out_size) {
    const float* x    = (const float*)d_in[0];   // (4, 10000, 256) fp32
    const int*   idx  = (const int*)d_in[1];     // (10000, 16) int32
    const float* mask = (const float*)d_in[2];   // (16, 256, 256) fp32
    const float* bias = (const float*)d_in[3];   // (256,) fp32
    float*       out  = (float*)d_out;           // (4, 10000, 256) fp32

    (void)in_sizes; (void)n_in; (void)out_size;

    static bool attr_set = false;
    if (!attr_set) {
        cudaFuncSetAttribute(piconv_mma_kernel,
                             cudaFuncAttributeMaxDynamicSharedMemorySize, DYN_SMEM);
        attr_set = true;
    }

    prologue_kernel<<<2274, 256>>>(x, mask);
    piconv_mma_kernel<<<dim3(MTILES, 4), NTHREADS, DYN_SMEM>>>(idx, bias, out);
}